// round 13
// baseline (speedup 1.0000x reference)
#include <cuda_runtime.h>
#include <cuda_bf16.h>

// LSTM_24936580121326 R13: R9 structure (gate-pair f32x2, 2 elem/thread)
// with weights moved __constant__ -> __shared__. Inline-asm fma2 operands are
// GPRs, so constant loads were LDC (floor 8 cyc/SMSP) — the co-binding port.
// Broadcast LDS.128 (floor 2) replaces them. Weights staged g_wtmp -> smem.

#define T_STEPS 49

typedef unsigned long long u64;

struct WPack {
    ulonglong2 w1if[8][4];   // layer1 W_hh rows (i,f) scaled 0.5
    ulonglong2 w1go[8][4];   // layer1 W_hh rows (g unscaled, o 0.5)
    ulonglong2 w2uif[8][4];  // layer2 W_ih
    ulonglong2 w2ugo[8][4];
    ulonglong2 w2vif[8][4];  // layer2 W_hh
    ulonglong2 w2vgo[8][4];
    u64 wx_if[8], wx_go[8];  // layer1 W_ih (input dim 1)
    u64 b1if[8], b1go[8];
    u64 b2if[8], b2go[8];
    float wlin[8];
    float blin;
    float pad;               // keep u64-aligned size
};

__device__ WPack g_wtmp;     // staged by prep kernel

__device__ __forceinline__ u64 pack2(float lo, float hi) {
    u64 r; asm("mov.b64 %0, {%1, %2};" : "=l"(r) : "f"(lo), "f"(hi)); return r;
}
__device__ __forceinline__ void unpack2(u64 v, float& lo, float& hi) {
    asm("mov.b64 {%0, %1}, %2;" : "=f"(lo), "=f"(hi) : "l"(v));
}
__device__ __forceinline__ u64 fma2(u64 a, u64 b, u64 c) {
    u64 d; asm("fma.rn.f32x2 %0, %1, %2, %3;" : "=l"(d) : "l"(a), "l"(b), "l"(c)); return d;
}
__device__ __forceinline__ float tanhf_hw(float x) {
    float y; asm("tanh.approx.f32 %0, %1;" : "=f"(y) : "f"(x)); return y;
}
__device__ __forceinline__ float sig_folded(float zh) {   // pre-halved input
    return fmaf(0.5f, tanhf_hw(zh), 0.5f);
}

// ---------------- preproc (identical math to R9) ----------------
__global__ void prep_weights_kernel(
    const float* __restrict__ W_ih0, const float* __restrict__ W_hh0,
    const float* __restrict__ b_ih0, const float* __restrict__ b_hh0,
    const float* __restrict__ W_ih1, const float* __restrict__ W_hh1,
    const float* __restrict__ b_ih1, const float* __restrict__ b_hh1,
    const float* __restrict__ W_lin, const float* __restrict__ b_lin)
{
    int tid = threadIdx.x;
    if (tid < 128) {
        int u = tid >> 4, q = (tid >> 2) & 3, s = tid & 3;
        int col = 2 * q + (s >> 1);
        int sel = s & 1;
        int idx = (u * 4 + q) * 4 + s;
        int gIF = u + 8 * sel;           // i or f
        int gGO = u + 16 + 8 * sel;      // g or o
        float scGO = sel ? 0.5f : 1.0f;
        ((float*)g_wtmp.w1if)[idx]  = 0.5f * W_hh0[gIF * 8 + col];
        ((float*)g_wtmp.w1go)[idx]  = scGO * W_hh0[gGO * 8 + col];
        ((float*)g_wtmp.w2uif)[idx] = 0.5f * W_ih1[gIF * 8 + col];
        ((float*)g_wtmp.w2ugo)[idx] = scGO * W_ih1[gGO * 8 + col];
        ((float*)g_wtmp.w2vif)[idx] = 0.5f * W_hh1[gIF * 8 + col];
        ((float*)g_wtmp.w2vgo)[idx] = scGO * W_hh1[gGO * 8 + col];
    }
    if (tid < 8) {
        int u = tid;
        float* p;
        p = (float*)g_wtmp.wx_if; p[2*u] = 0.5f * W_ih0[u];      p[2*u+1] = 0.5f * W_ih0[u+8];
        p = (float*)g_wtmp.wx_go; p[2*u] =        W_ih0[u+16];   p[2*u+1] = 0.5f * W_ih0[u+24];
        p = (float*)g_wtmp.b1if;  p[2*u] = 0.5f*(b_ih0[u]+b_hh0[u]);
                                  p[2*u+1] = 0.5f*(b_ih0[u+8]+b_hh0[u+8]);
        p = (float*)g_wtmp.b1go;  p[2*u] =       (b_ih0[u+16]+b_hh0[u+16]);
                                  p[2*u+1] = 0.5f*(b_ih0[u+24]+b_hh0[u+24]);
        p = (float*)g_wtmp.b2if;  p[2*u] = 0.5f*(b_ih1[u]+b_hh1[u]);
                                  p[2*u+1] = 0.5f*(b_ih1[u+8]+b_hh1[u+8]);
        p = (float*)g_wtmp.b2go;  p[2*u] =       (b_ih1[u+16]+b_hh1[u+16]);
                                  p[2*u+1] = 0.5f*(b_ih1[u+24]+b_hh1[u+24]);
        g_wtmp.wlin[u] = W_lin[u];
    }
    if (tid == 0) g_wtmp.blin = b_lin[0];
}

// ---------------- fused LSTM: weights in shared, 2 elements/thread ---------
__global__ void __launch_bounds__(256) lstm_fused_kernel(
    const float* __restrict__ X, float* __restrict__ out, int Bn)
{
    __shared__ WPack s_w;

    int tid = threadIdx.x;
    // bulk copy g_wtmp -> s_w (u64 granularity)
    {
        const u64* src = (const u64*)&g_wtmp;
        u64* dst = (u64*)&s_w;
        const int n64 = (int)(sizeof(WPack) / 8);
        for (int i = tid; i < n64; i += 256) dst[i] = src[i];
    }
    __syncthreads();

    int bA = blockIdx.x * 512 + tid;
    int bB = bA + 256;
    bool vA = bA < Bn, vB = bB < Bn;

    u64 hp1A[8], hp2A[8], hp1B[8], hp2B[8];   // {h,h} splats
    float c1A[8], c2A[8], c1B[8], c2B[8];
    u64 zero = pack2(0.f, 0.f);
#pragma unroll
    for (int u = 0; u < 8; ++u) {
        hp1A[u] = hp2A[u] = hp1B[u] = hp2B[u] = zero;
        c1A[u] = c2A[u] = c1B[u] = c2B[u] = 0.f;
    }

    const float* __restrict__ xpA = X + (long long)(vA ? bA : 0) * T_STEPS;
    const float* __restrict__ xpB = X + (long long)(vB ? bB : 0) * T_STEPS;

#pragma unroll 1
    for (int t = 0; t < T_STEPS; ++t) {
        float xA = __ldg(xpA + t);
        float xB = __ldg(xpB + t);
        u64 xxA = pack2(xA, xA);
        u64 xxB = pack2(xB, xB);

        // ---------- layer 1 ----------
        u64 hn1A[8], hn1B[8];
#pragma unroll
        for (int u = 0; u < 8; ++u) {
            u64 wxi = s_w.wx_if[u], wxg = s_w.wx_go[u];
            u64 bi  = s_w.b1if[u],  bg  = s_w.b1go[u];
            u64 aifA = fma2(wxi, xxA, bi);
            u64 agoA = fma2(wxg, xxA, bg);
            u64 aifB = fma2(wxi, xxB, bi);
            u64 agoB = fma2(wxg, xxB, bg);
#pragma unroll
            for (int q = 0; q < 4; ++q) {
                ulonglong2 wi = s_w.w1if[u][q];
                ulonglong2 wg = s_w.w1go[u][q];
                aifA = fma2(wi.x, hp1A[2*q],   aifA);
                aifA = fma2(wi.y, hp1A[2*q+1], aifA);
                agoA = fma2(wg.x, hp1A[2*q],   agoA);
                agoA = fma2(wg.y, hp1A[2*q+1], agoA);
                aifB = fma2(wi.x, hp1B[2*q],   aifB);
                aifB = fma2(wi.y, hp1B[2*q+1], aifB);
                agoB = fma2(wg.x, hp1B[2*q],   agoB);
                agoB = fma2(wg.y, hp1B[2*q+1], agoB);
            }
            {
                float zi, zf, zg, zo;
                unpack2(aifA, zi, zf);
                unpack2(agoA, zg, zo);
                float ig = sig_folded(zi), fg = sig_folded(zf);
                float gg = tanhf_hw(zg),  og = sig_folded(zo);
                c1A[u] = fmaf(fg, c1A[u], ig * gg);
                float h = og * tanhf_hw(c1A[u]);
                hn1A[u] = pack2(h, h);
            }
            {
                float zi, zf, zg, zo;
                unpack2(aifB, zi, zf);
                unpack2(agoB, zg, zo);
                float ig = sig_folded(zi), fg = sig_folded(zf);
                float gg = tanhf_hw(zg),  og = sig_folded(zo);
                c1B[u] = fmaf(fg, c1B[u], ig * gg);
                float h = og * tanhf_hw(c1B[u]);
                hn1B[u] = pack2(h, h);
            }
        }

        // ---------- layer 2 ----------
        u64 hn2A[8], hn2B[8];
#pragma unroll
        for (int u = 0; u < 8; ++u) {
            u64 bi = s_w.b2if[u], bg = s_w.b2go[u];
            u64 aifA = bi, agoA = bg, aifB = bi, agoB = bg;
#pragma unroll
            for (int q = 0; q < 4; ++q) {
                ulonglong2 ui = s_w.w2uif[u][q];
                ulonglong2 ug = s_w.w2ugo[u][q];
                aifA = fma2(ui.x, hn1A[2*q],   aifA);
                aifA = fma2(ui.y, hn1A[2*q+1], aifA);
                agoA = fma2(ug.x, hn1A[2*q],   agoA);
                agoA = fma2(ug.y, hn1A[2*q+1], agoA);
                aifB = fma2(ui.x, hn1B[2*q],   aifB);
                aifB = fma2(ui.y, hn1B[2*q+1], aifB);
                agoB = fma2(ug.x, hn1B[2*q],   agoB);
                agoB = fma2(ug.y, hn1B[2*q+1], agoB);
            }
#pragma unroll
            for (int q = 0; q < 4; ++q) {
                ulonglong2 vi = s_w.w2vif[u][q];
                ulonglong2 vg = s_w.w2vgo[u][q];
                aifA = fma2(vi.x, hp2A[2*q],   aifA);
                aifA = fma2(vi.y, hp2A[2*q+1], aifA);
                agoA = fma2(vg.x, hp2A[2*q],   agoA);
                agoA = fma2(vg.y, hp2A[2*q+1], agoA);
                aifB = fma2(vi.x, hp2B[2*q],   aifB);
                aifB = fma2(vi.y, hp2B[2*q+1], aifB);
                agoB = fma2(vg.x, hp2B[2*q],   agoB);
                agoB = fma2(vg.y, hp2B[2*q+1], agoB);
            }
            {
                float zi, zf, zg, zo;
                unpack2(aifA, zi, zf);
                unpack2(agoA, zg, zo);
                float ig = sig_folded(zi), fg = sig_folded(zf);
                float gg = tanhf_hw(zg),  og = sig_folded(zo);
                c2A[u] = fmaf(fg, c2A[u], ig * gg);
                float h = og * tanhf_hw(c2A[u]);
                hn2A[u] = pack2(h, h);
            }
            {
                float zi, zf, zg, zo;
                unpack2(aifB, zi, zf);
                unpack2(agoB, zg, zo);
                float ig = sig_folded(zi), fg = sig_folded(zf);
                float gg = tanhf_hw(zg),  og = sig_folded(zo);
                c2B[u] = fmaf(fg, c2B[u], ig * gg);
                float h = og * tanhf_hw(c2B[u]);
                hn2B[u] = pack2(h, h);
            }
        }

#pragma unroll
        for (int u = 0; u < 8; ++u) {
            hp1A[u] = hn1A[u]; hp2A[u] = hn2A[u];
            hp1B[u] = hn1B[u]; hp2B[u] = hn2B[u];
        }
    }

    // ---------- relu -> linear -> relu ----------
    float accA = s_w.blin, accB = s_w.blin;
#pragma unroll
    for (int u = 0; u < 8; ++u) {
        float hA, hB, d;
        unpack2(hp2A[u], hA, d);
        unpack2(hp2B[u], hB, d);
        accA = fmaf(s_w.wlin[u], fmaxf(hA, 0.0f), accA);
        accB = fmaf(s_w.wlin[u], fmaxf(hB, 0.0f), accB);
    }
    if (vA) out[bA] = fmaxf(accA, 0.0f);
    if (vB) out[bB] = fmaxf(accB, 0.0f);
}

extern "C" void kernel_launch(void* const* d_in, const int* in_sizes, int n_in,
                              void* d_out, int out_size) {
    const float* X     = (const float*)d_in[0];
    const float* W_ih0 = (const float*)d_in[1];
    const float* W_hh0 = (const float*)d_in[2];
    const float* b_ih0 = (const float*)d_in[3];
    const float* b_hh0 = (const float*)d_in[4];
    const float* W_ih1 = (const float*)d_in[5];
    const float* W_hh1 = (const float*)d_in[6];
    const float* b_ih1 = (const float*)d_in[7];
    const float* b_hh1 = (const float*)d_in[8];
    const float* W_lin = (const float*)d_in[9];
    const float* b_lin = (const float*)d_in[10];

    int Bn = out_size;

    prep_weights_kernel<<<1, 256>>>(
        W_ih0, W_hh0, b_ih0, b_hh0,
        W_ih1, W_hh1, b_ih1, b_hh1, W_lin, b_lin);

    int blocks = (Bn + 511) / 512;
    lstm_fused_kernel<<<blocks, 256>>>(X, (float*)d_out, Bn);
}

// round 14
// speedup vs baseline: 1.1929x; 1.1929x over previous
#include <cuda_runtime.h>
#include <cuda_bf16.h>

// LSTM_24936580121326 R14: R9 structure (gate-pair f32x2, 2 elem/thread) with
// HYBRID weight placement: layer-1 weights + biases in __constant__ (LDC),
// layer-2 matvec weights in __shared__ (LDS) — splits the half-rate constant
// port (floor 8/SMSP) against the cheap LDS port (floor 2/SMSP).

#define T_STEPS 49

typedef unsigned long long u64;

struct WConst {
    ulonglong2 w1if[8][4];   // layer1 W_hh rows (i,f) scaled 0.5
    ulonglong2 w1go[8][4];   // layer1 W_hh rows (g unscaled, o 0.5)
    u64 wx_if[8], wx_go[8];  // layer1 W_ih (input dim 1)
    u64 b1if[8], b1go[8];
    u64 b2if[8], b2go[8];
    float wlin[8];
    float blin;
};
struct WSmem {
    ulonglong2 w2uif[8][4];  // layer2 W_ih
    ulonglong2 w2ugo[8][4];
    ulonglong2 w2vif[8][4];  // layer2 W_hh
    ulonglong2 w2vgo[8][4];
};

__device__   WConst g_ctmp;
__device__   WSmem  g_stmp;
__constant__ WConst c_w;

__device__ __forceinline__ u64 pack2(float lo, float hi) {
    u64 r; asm("mov.b64 %0, {%1, %2};" : "=l"(r) : "f"(lo), "f"(hi)); return r;
}
__device__ __forceinline__ void unpack2(u64 v, float& lo, float& hi) {
    asm("mov.b64 {%0, %1}, %2;" : "=f"(lo), "=f"(hi) : "l"(v));
}
__device__ __forceinline__ u64 fma2(u64 a, u64 b, u64 c) {
    u64 d; asm("fma.rn.f32x2 %0, %1, %2, %3;" : "=l"(d) : "l"(a), "l"(b), "l"(c)); return d;
}
__device__ __forceinline__ float tanhf_hw(float x) {
    float y; asm("tanh.approx.f32 %0, %1;" : "=f"(y) : "f"(x)); return y;
}
__device__ __forceinline__ float sig_folded(float zh) {   // pre-halved input
    return fmaf(0.5f, tanhf_hw(zh), 0.5f);
}

// ---------------- preproc: stage both packs ----------------
__global__ void prep_weights_kernel(
    const float* __restrict__ W_ih0, const float* __restrict__ W_hh0,
    const float* __restrict__ b_ih0, const float* __restrict__ b_hh0,
    const float* __restrict__ W_ih1, const float* __restrict__ W_hh1,
    const float* __restrict__ b_ih1, const float* __restrict__ b_hh1,
    const float* __restrict__ W_lin, const float* __restrict__ b_lin)
{
    int tid = threadIdx.x;
    if (tid < 128) {
        int u = tid >> 4, q = (tid >> 2) & 3, s = tid & 3;
        int col = 2 * q + (s >> 1);
        int sel = s & 1;
        int idx = (u * 4 + q) * 4 + s;
        int gIF = u + 8 * sel;           // i or f
        int gGO = u + 16 + 8 * sel;      // g or o
        float scGO = sel ? 0.5f : 1.0f;
        ((float*)g_ctmp.w1if)[idx]  = 0.5f * W_hh0[gIF * 8 + col];
        ((float*)g_ctmp.w1go)[idx]  = scGO * W_hh0[gGO * 8 + col];
        ((float*)g_stmp.w2uif)[idx] = 0.5f * W_ih1[gIF * 8 + col];
        ((float*)g_stmp.w2ugo)[idx] = scGO * W_ih1[gGO * 8 + col];
        ((float*)g_stmp.w2vif)[idx] = 0.5f * W_hh1[gIF * 8 + col];
        ((float*)g_stmp.w2vgo)[idx] = scGO * W_hh1[gGO * 8 + col];
    }
    if (tid < 8) {
        int u = tid;
        float* p;
        p = (float*)g_ctmp.wx_if; p[2*u] = 0.5f * W_ih0[u];      p[2*u+1] = 0.5f * W_ih0[u+8];
        p = (float*)g_ctmp.wx_go; p[2*u] =        W_ih0[u+16];   p[2*u+1] = 0.5f * W_ih0[u+24];
        p = (float*)g_ctmp.b1if;  p[2*u] = 0.5f*(b_ih0[u]+b_hh0[u]);
                                  p[2*u+1] = 0.5f*(b_ih0[u+8]+b_hh0[u+8]);
        p = (float*)g_ctmp.b1go;  p[2*u] =       (b_ih0[u+16]+b_hh0[u+16]);
                                  p[2*u+1] = 0.5f*(b_ih0[u+24]+b_hh0[u+24]);
        p = (float*)g_ctmp.b2if;  p[2*u] = 0.5f*(b_ih1[u]+b_hh1[u]);
                                  p[2*u+1] = 0.5f*(b_ih1[u+8]+b_hh1[u+8]);
        p = (float*)g_ctmp.b2go;  p[2*u] =       (b_ih1[u+16]+b_hh1[u+16]);
                                  p[2*u+1] = 0.5f*(b_ih1[u+24]+b_hh1[u+24]);
        g_ctmp.wlin[u] = W_lin[u];
    }
    if (tid == 0) g_ctmp.blin = b_lin[0];
}

// ---------------- fused LSTM: hybrid weights, 2 elements/thread ------------
__global__ void __launch_bounds__(256) lstm_fused_kernel(
    const float* __restrict__ X, float* __restrict__ out, int Bn)
{
    __shared__ WSmem s_w;

    int tid = threadIdx.x;
    {   // bulk copy layer-2 weights into smem (2 KB, 256 u64, 1 per thread)
        const u64* src = (const u64*)&g_stmp;
        u64* dst = (u64*)&s_w;
        const int n64 = (int)(sizeof(WSmem) / 8);
        for (int i = tid; i < n64; i += 256) dst[i] = src[i];
    }
    __syncthreads();

    int bA = blockIdx.x * 512 + tid;
    int bB = bA + 256;
    bool vA = bA < Bn, vB = bB < Bn;

    u64 hp1A[8], hp2A[8], hp1B[8], hp2B[8];   // {h,h} splats
    float c1A[8], c2A[8], c1B[8], c2B[8];
    u64 zero = pack2(0.f, 0.f);
#pragma unroll
    for (int u = 0; u < 8; ++u) {
        hp1A[u] = hp2A[u] = hp1B[u] = hp2B[u] = zero;
        c1A[u] = c2A[u] = c1B[u] = c2B[u] = 0.f;
    }

    const float* __restrict__ xpA = X + (long long)(vA ? bA : 0) * T_STEPS;
    const float* __restrict__ xpB = X + (long long)(vB ? bB : 0) * T_STEPS;

#pragma unroll 1
    for (int t = 0; t < T_STEPS; ++t) {
        float xA = __ldg(xpA + t);
        float xB = __ldg(xpB + t);
        u64 xxA = pack2(xA, xA);
        u64 xxB = pack2(xB, xB);

        // ---------- layer 1 (constant weights) ----------
        u64 hn1A[8], hn1B[8];
#pragma unroll
        for (int u = 0; u < 8; ++u) {
            u64 wxi = c_w.wx_if[u], wxg = c_w.wx_go[u];
            u64 bi  = c_w.b1if[u],  bg  = c_w.b1go[u];
            u64 aifA = fma2(wxi, xxA, bi);
            u64 agoA = fma2(wxg, xxA, bg);
            u64 aifB = fma2(wxi, xxB, bi);
            u64 agoB = fma2(wxg, xxB, bg);
#pragma unroll
            for (int q = 0; q < 4; ++q) {
                ulonglong2 wi = c_w.w1if[u][q];
                ulonglong2 wg = c_w.w1go[u][q];
                aifA = fma2(wi.x, hp1A[2*q],   aifA);
                aifA = fma2(wi.y, hp1A[2*q+1], aifA);
                agoA = fma2(wg.x, hp1A[2*q],   agoA);
                agoA = fma2(wg.y, hp1A[2*q+1], agoA);
                aifB = fma2(wi.x, hp1B[2*q],   aifB);
                aifB = fma2(wi.y, hp1B[2*q+1], aifB);
                agoB = fma2(wg.x, hp1B[2*q],   agoB);
                agoB = fma2(wg.y, hp1B[2*q+1], agoB);
            }
            {
                float zi, zf, zg, zo;
                unpack2(aifA, zi, zf);
                unpack2(agoA, zg, zo);
                float ig = sig_folded(zi), fg = sig_folded(zf);
                float gg = tanhf_hw(zg),  og = sig_folded(zo);
                c1A[u] = fmaf(fg, c1A[u], ig * gg);
                float h = og * tanhf_hw(c1A[u]);
                hn1A[u] = pack2(h, h);
            }
            {
                float zi, zf, zg, zo;
                unpack2(aifB, zi, zf);
                unpack2(agoB, zg, zo);
                float ig = sig_folded(zi), fg = sig_folded(zf);
                float gg = tanhf_hw(zg),  og = sig_folded(zo);
                c1B[u] = fmaf(fg, c1B[u], ig * gg);
                float h = og * tanhf_hw(c1B[u]);
                hn1B[u] = pack2(h, h);
            }
        }

        // ---------- layer 2 (shared weights, constant biases) ----------
        u64 hn2A[8], hn2B[8];
#pragma unroll
        for (int u = 0; u < 8; ++u) {
            u64 bi = c_w.b2if[u], bg = c_w.b2go[u];
            u64 aifA = bi, agoA = bg, aifB = bi, agoB = bg;
#pragma unroll
            for (int q = 0; q < 4; ++q) {
                ulonglong2 ui = s_w.w2uif[u][q];
                ulonglong2 ug = s_w.w2ugo[u][q];
                aifA = fma2(ui.x, hn1A[2*q],   aifA);
                aifA = fma2(ui.y, hn1A[2*q+1], aifA);
                agoA = fma2(ug.x, hn1A[2*q],   agoA);
                agoA = fma2(ug.y, hn1A[2*q+1], agoA);
                aifB = fma2(ui.x, hn1B[2*q],   aifB);
                aifB = fma2(ui.y, hn1B[2*q+1], aifB);
                agoB = fma2(ug.x, hn1B[2*q],   agoB);
                agoB = fma2(ug.y, hn1B[2*q+1], agoB);
            }
#pragma unroll
            for (int q = 0; q < 4; ++q) {
                ulonglong2 vi = s_w.w2vif[u][q];
                ulonglong2 vg = s_w.w2vgo[u][q];
                aifA = fma2(vi.x, hp2A[2*q],   aifA);
                aifA = fma2(vi.y, hp2A[2*q+1], aifA);
                agoA = fma2(vg.x, hp2A[2*q],   agoA);
                agoA = fma2(vg.y, hp2A[2*q+1], agoA);
                aifB = fma2(vi.x, hp2B[2*q],   aifB);
                aifB = fma2(vi.y, hp2B[2*q+1], aifB);
                agoB = fma2(vg.x, hp2B[2*q],   agoB);
                agoB = fma2(vg.y, hp2B[2*q+1], agoB);
            }
            {
                float zi, zf, zg, zo;
                unpack2(aifA, zi, zf);
                unpack2(agoA, zg, zo);
                float ig = sig_folded(zi), fg = sig_folded(zf);
                float gg = tanhf_hw(zg),  og = sig_folded(zo);
                c2A[u] = fmaf(fg, c2A[u], ig * gg);
                float h = og * tanhf_hw(c2A[u]);
                hn2A[u] = pack2(h, h);
            }
            {
                float zi, zf, zg, zo;
                unpack2(aifB, zi, zf);
                unpack2(agoB, zg, zo);
                float ig = sig_folded(zi), fg = sig_folded(zf);
                float gg = tanhf_hw(zg),  og = sig_folded(zo);
                c2B[u] = fmaf(fg, c2B[u], ig * gg);
                float h = og * tanhf_hw(c2B[u]);
                hn2B[u] = pack2(h, h);
            }
        }

#pragma unroll
        for (int u = 0; u < 8; ++u) {
            hp1A[u] = hn1A[u]; hp2A[u] = hn2A[u];
            hp1B[u] = hn1B[u]; hp2B[u] = hn2B[u];
        }
    }

    // ---------- relu -> linear -> relu ----------
    float accA = c_w.blin, accB = c_w.blin;
#pragma unroll
    for (int u = 0; u < 8; ++u) {
        float hA, hB, d;
        unpack2(hp2A[u], hA, d);
        unpack2(hp2B[u], hB, d);
        accA = fmaf(c_w.wlin[u], fmaxf(hA, 0.0f), accA);
        accB = fmaf(c_w.wlin[u], fmaxf(hB, 0.0f), accB);
    }
    if (vA) out[bA] = fmaxf(accA, 0.0f);
    if (vB) out[bB] = fmaxf(accB, 0.0f);
}

extern "C" void kernel_launch(void* const* d_in, const int* in_sizes, int n_in,
                              void* d_out, int out_size) {
    const float* X     = (const float*)d_in[0];
    const float* W_ih0 = (const float*)d_in[1];
    const float* W_hh0 = (const float*)d_in[2];
    const float* b_ih0 = (const float*)d_in[3];
    const float* b_hh0 = (const float*)d_in[4];
    const float* W_ih1 = (const float*)d_in[5];
    const float* W_hh1 = (const float*)d_in[6];
    const float* b_ih1 = (const float*)d_in[7];
    const float* b_hh1 = (const float*)d_in[8];
    const float* W_lin = (const float*)d_in[9];
    const float* b_lin = (const float*)d_in[10];

    int Bn = out_size;

    prep_weights_kernel<<<1, 256>>>(
        W_ih0, W_hh0, b_ih0, b_hh0,
        W_ih1, W_hh1, b_ih1, b_hh1, W_lin, b_lin);

    // Promote the layer-1/bias pack to constant memory (capturable D2D copy).
    void* src = nullptr;
    cudaGetSymbolAddress(&src, g_ctmp);
    cudaMemcpyToSymbolAsync(c_w, src, sizeof(WConst), 0,
                            cudaMemcpyDeviceToDevice, 0);

    int blocks = (Bn + 511) / 512;
    lstm_fused_kernel<<<blocks, 256>>>(X, (float*)d_out, Bn);
}